// round 1
// baseline (speedup 1.0000x reference)
#include <cuda_runtime.h>

// Problem constants (fixed by the reference):
//   N rows (in_sizes[0]/32), DM=32 per modality, DIN=128, DOUT=64.
// out[i] = W2 @ relu(W1 @ x_i + b1) + b2  for i >= 4
// rows 0..3 all equal W2 @ relu(W1 @ mean(x_0..3) + b1) + b2

#define BM       64
#define THREADS  256
#define XS_STRIDE 132   // 128 + 4 pad (bank-safe, mult of 4 for float4)
#define W1_STRIDE 68    // 64 + 4 pad
#define W2_STRIDE 68
#define HS_STRIDE 68

// smem layout (floats):
//   Xs  : 64*132 = 8448   (reused as Hs[64*68] for stage 2)
//   W1t : 128*68 = 8704   (k-major transpose of W1)
//   W2t : 64*68  = 4352   (k-major transpose of W2)
//   b1s : 64
//   b2s : 64
#define SMEM_FLOATS (64*XS_STRIDE + 128*W1_STRIDE + 64*W2_STRIDE + 64 + 64)
#define SMEM_BYTES  (SMEM_FLOATS * 4)

__device__ __forceinline__ unsigned long long splat2(float a) {
    unsigned long long r;
    asm("mov.b64 %0, {%1, %1};" : "=l"(r) : "r"(__float_as_uint(a)));
    return r;
}

__device__ __forceinline__ void fma2(unsigned long long& d,
                                     unsigned long long a,
                                     unsigned long long b) {
    // packed dual-fp32 FMA (SASS FFMA2) — PTX-only path on sm_103a
    asm("fma.rn.f32x2 %0, %1, %2, %0;" : "+l"(d) : "l"(a), "l"(b));
}

__device__ __forceinline__ float2 unpack2(unsigned long long v) {
    unsigned lo, hi;
    asm("mov.b64 {%0, %1}, %2;" : "=r"(lo), "=r"(hi) : "l"(v));
    float2 r;
    r.x = __uint_as_float(lo);
    r.y = __uint_as_float(hi);
    return r;
}

__global__ void __launch_bounds__(THREADS, 2)
gcn_mlp_kernel(const float* __restrict__ audio,
               const float* __restrict__ video,
               const float* __restrict__ x1,
               const float* __restrict__ x2,
               const float* __restrict__ W1,
               const float* __restrict__ b1,
               const float* __restrict__ W2,
               const float* __restrict__ b2,
               float* __restrict__ out,
               int nrows) {
    extern __shared__ float smem[];
    float* Xs  = smem;
    float* W1t = Xs  + 64 * XS_STRIDE;
    float* W2t = W1t + 128 * W1_STRIDE;
    float* b1s = W2t + 64 * W2_STRIDE;
    float* b2s = b1s + 64;
    float* Hs  = Xs;   // reused after stage-1 sync

    const int tid = threadIdx.x;
    const long row0 = (long)blockIdx.x * BM;

    // ---- stage 0: cooperative loads ----
    {
        const float* mods[4] = {audio, video, x1, x2};
#pragma unroll
        for (int m = 0; m < 4; m++) {
            const float4* src = (const float4*)(mods[m] + row0 * 32);
#pragma unroll
            for (int it = 0; it < 2; it++) {
                int idx = tid + it * THREADS;       // 512 float4s
                int r  = idx >> 3;
                int c4 = idx & 7;
                float4 v = src[r * 8 + c4];
                *(float4*)&Xs[r * XS_STRIDE + m * 32 + c4 * 4] = v;
            }
        }
        // W1 [64 out][128 in] -> W1t[k][o]
#pragma unroll
        for (int it = 0; it < 32; it++) {
            int idx = tid + it * THREADS;           // 8192 elems
            int o = idx >> 7, k = idx & 127;
            W1t[k * W1_STRIDE + o] = W1[idx];
        }
        // W2 [64][64] -> W2t[k][o]
#pragma unroll
        for (int it = 0; it < 16; it++) {
            int idx = tid + it * THREADS;           // 4096 elems
            int o = idx >> 6, k = idx & 63;
            W2t[k * W2_STRIDE + o] = W2[idx];
        }
        if (tid < 64) { b1s[tid] = b1[tid]; b2s[tid] = b2[tid]; }
    }
    __syncthreads();

    const int tx = tid & 15;   // output cols tx*4 .. tx*4+3
    const int ty = tid >> 4;   // rows ty*4 .. ty*4+3

    // ---- stage 1: H = relu(X @ W1^T + b1), K = 128 ----
    unsigned long long acc[4][2];
#pragma unroll
    for (int i = 0; i < 4; i++) { acc[i][0] = 0ull; acc[i][1] = 0ull; }

    {
        const float* xrow = &Xs[(ty * 4) * XS_STRIDE];
        const float* wcol = &W1t[tx * 4];
#pragma unroll 8
        for (int k = 0; k < 128; k++) {
            ulonglong2 bb = *(const ulonglong2*)&wcol[k * W1_STRIDE];
#pragma unroll
            for (int i = 0; i < 4; i++) {
                unsigned long long a2 = splat2(xrow[i * XS_STRIDE + k]);
                fma2(acc[i][0], a2, bb.x);
                fma2(acc[i][1], a2, bb.y);
            }
        }
    }

    float bv0 = b1s[tx * 4 + 0], bv1 = b1s[tx * 4 + 1];
    float bv2 = b1s[tx * 4 + 2], bv3 = b1s[tx * 4 + 3];

    __syncthreads();   // everyone done reading Xs before Hs overwrites it

#pragma unroll
    for (int i = 0; i < 4; i++) {
        float2 v0 = unpack2(acc[i][0]);
        float2 v1 = unpack2(acc[i][1]);
        float4 hv;
        hv.x = fmaxf(v0.x + bv0, 0.f);
        hv.y = fmaxf(v0.y + bv1, 0.f);
        hv.z = fmaxf(v1.x + bv2, 0.f);
        hv.w = fmaxf(v1.y + bv3, 0.f);
        *(float4*)&Hs[(ty * 4 + i) * HS_STRIDE + tx * 4] = hv;
    }
    __syncthreads();

    // ---- stage 2: OUT = H @ W2^T + b2, K = 64 ----
#pragma unroll
    for (int i = 0; i < 4; i++) { acc[i][0] = 0ull; acc[i][1] = 0ull; }

    {
        const float* hrow = &Hs[(ty * 4) * HS_STRIDE];
        const float* wcol = &W2t[tx * 4];
#pragma unroll 8
        for (int k = 0; k < 64; k++) {
            ulonglong2 bb = *(const ulonglong2*)&wcol[k * W2_STRIDE];
#pragma unroll
            for (int i = 0; i < 4; i++) {
                unsigned long long a2 = splat2(hrow[i * HS_STRIDE + k]);
                fma2(acc[i][0], a2, bb.x);
                fma2(acc[i][1], a2, bb.y);
            }
        }
    }

    float c0 = b2s[tx * 4 + 0], c1 = b2s[tx * 4 + 1];
    float c2 = b2s[tx * 4 + 2], c3 = b2s[tx * 4 + 3];

#pragma unroll
    for (int i = 0; i < 4; i++) {
        float2 v0 = unpack2(acc[i][0]);
        float2 v1 = unpack2(acc[i][1]);
        float4 ov;
        ov.x = v0.x + c0;
        ov.y = v0.y + c1;
        ov.z = v1.x + c2;
        ov.w = v1.y + c3;
        long row = row0 + ty * 4 + i;
        *(float4*)&out[row * 64 + tx * 4] = ov;
    }
}

// Rows 0..3: all four equal W2 @ relu(W1 @ mean(x_0..3) + b1) + b2
__global__ void gcn_fixup_kernel(const float* __restrict__ audio,
                                 const float* __restrict__ video,
                                 const float* __restrict__ x1,
                                 const float* __restrict__ x2,
                                 const float* __restrict__ W1,
                                 const float* __restrict__ b1,
                                 const float* __restrict__ W2,
                                 const float* __restrict__ b2,
                                 float* __restrict__ out) {
    __shared__ float xbar[128];
    __shared__ float h[64];
    const int t = threadIdx.x;   // 128 threads

    {
        const float* mods[4] = {audio, video, x1, x2};
        const float* p = mods[t >> 5];
        int c = t & 31;
        xbar[t] = 0.25f * (p[c] + p[32 + c] + p[64 + c] + p[96 + c]);
    }
    __syncthreads();

    if (t < 64) {
        float s = 0.f;
        const float* wr = &W1[t * 128];
#pragma unroll 8
        for (int k = 0; k < 128; k++) s = fmaf(wr[k], xbar[k], s);
        h[t] = fmaxf(s + b1[t], 0.f);
    }
    __syncthreads();

    if (t < 64) {
        float s = 0.f;
        const float* wr = &W2[t * 64];
#pragma unroll 8
        for (int j = 0; j < 64; j++) s = fmaf(wr[j], h[j], s);
        float v = s + b2[t];
        out[0 * 64 + t] = v;
        out[1 * 64 + t] = v;
        out[2 * 64 + t] = v;
        out[3 * 64 + t] = v;
    }
}

extern "C" void kernel_launch(void* const* d_in, const int* in_sizes, int n_in,
                              void* d_out, int out_size) {
    const float* audio = (const float*)d_in[0];
    const float* video = (const float*)d_in[1];
    const float* x1    = (const float*)d_in[2];
    const float* x2    = (const float*)d_in[3];
    const float* W1    = (const float*)d_in[4];
    const float* b1    = (const float*)d_in[5];
    const float* W2    = (const float*)d_in[6];
    const float* b2    = (const float*)d_in[7];
    float* out = (float*)d_out;

    int nrows = in_sizes[0] / 32;          // audio is [N, 32]
    int grid  = nrows / BM;                // N = 1048576 -> 16384 blocks

    cudaFuncSetAttribute(gcn_mlp_kernel,
                         cudaFuncAttributeMaxDynamicSharedMemorySize,
                         SMEM_BYTES);

    gcn_mlp_kernel<<<grid, THREADS, SMEM_BYTES>>>(
        audio, video, x1, x2, W1, b1, W2, b2, out, nrows);

    gcn_fixup_kernel<<<1, 128>>>(audio, video, x1, x2, W1, b1, W2, b2, out);
}

// round 3
// speedup vs baseline: 2.3546x; 2.3546x over previous
#include <cuda_runtime.h>
#include <cuda_bf16.h>
#include <cstdint>

// ============================================================================
// out[i] = W2 @ relu(W1 @ x_i + b1) + b2  for i >= 4
// rows 0..3 all equal W2 @ relu(W1 @ mean(x_0..3) + b1) + b2
//
// Tensor-core path via mma.sync m16n8k16 bf16 (plain sm_103 — no 'a' features).
// fp32 accuracy recovered with 2-way bf16 split, 3 accumulation passes.
// ============================================================================

#define TM       256      // rows per CTA
#define THREADS  512      // 16 warps x 16 rows

// Pre-split weight scratch layout (bytes), shared by prep kernel and smem:
//   W1hi: [n=0..63][k=0..127] bf16, row stride 272  -> 17408 B
//   W1lo: same                                        +17408
//   W2hi: [n=0..63][k=0..63]  bf16, row stride 144  ->  9216 B
//   W2lo: same
#define S_W1     272
#define S_W2     144
#define OFF_W1HI 0
#define OFF_W1LO 17408
#define OFF_W2HI 34816
#define OFF_W2LO 44032
#define WBYTES   53248

__device__ uint4 g_W[WBYTES / 16];

__device__ __forceinline__ uint32_t smem_u32(const void* p) {
    uint32_t a;
    asm("{ .reg .u64 t; cvta.to.shared.u64 t, %1; cvt.u32.u64 %0, t; }"
        : "=r"(a) : "l"(p));
    return a;
}

__device__ __forceinline__ uint16_t bf16_bits(float f) {
    __nv_bfloat16 h = __float2bfloat16(f);
    return *(uint16_t*)&h;
}
__device__ __forceinline__ float bf16_val(uint16_t b) {
    __nv_bfloat16 h = *(__nv_bfloat16*)&b;
    return __bfloat162float(h);
}

// split two fp32 into packed bf16x2 hi and lo (residual) fragments
__device__ __forceinline__ void split_pack(float x0, float x1,
                                           uint32_t& hi, uint32_t& lo) {
    uint16_t h0 = bf16_bits(x0);
    uint16_t h1 = bf16_bits(x1);
    uint16_t l0 = bf16_bits(x0 - bf16_val(h0));
    uint16_t l1 = bf16_bits(x1 - bf16_val(h1));
    hi = (uint32_t)h0 | ((uint32_t)h1 << 16);
    lo = (uint32_t)l0 | ((uint32_t)l1 << 16);
}

__device__ __forceinline__ void ldsm4(uint32_t* r, uint32_t addr) {
    asm volatile("ldmatrix.sync.aligned.m8n8.x4.shared.b16 {%0,%1,%2,%3}, [%4];"
                 : "=r"(r[0]), "=r"(r[1]), "=r"(r[2]), "=r"(r[3])
                 : "r"(addr));
}

__device__ __forceinline__ void mma_bf16(float* d, const uint32_t* a,
                                         uint32_t b0, uint32_t b1) {
    asm volatile(
        "mma.sync.aligned.m16n8k16.row.col.f32.bf16.bf16.f32 "
        "{%0,%1,%2,%3}, {%4,%5,%6,%7}, {%8,%9}, {%0,%1,%2,%3};"
        : "+f"(d[0]), "+f"(d[1]), "+f"(d[2]), "+f"(d[3])
        : "r"(a[0]), "r"(a[1]), "r"(a[2]), "r"(a[3]), "r"(b0), "r"(b1));
}

// ---------------------------------------------------------------------------
// prep: split W1/W2 to bf16 hi/lo in the exact smem layout
// ---------------------------------------------------------------------------
__global__ void prep_weights(const float* __restrict__ W1,
                             const float* __restrict__ W2) {
    uint16_t* g = (uint16_t*)g_W;
    int t = threadIdx.x;
    for (int idx = t; idx < 64 * 128; idx += 256) {   // W1 [n=64][k=128]
        int n = idx >> 7, k = idx & 127;
        float x = W1[idx];
        uint16_t hb = bf16_bits(x);
        uint16_t lb = bf16_bits(x - bf16_val(hb));
        g[(OFF_W1HI >> 1) + n * (S_W1 >> 1) + k] = hb;
        g[(OFF_W1LO >> 1) + n * (S_W1 >> 1) + k] = lb;
    }
    for (int idx = t; idx < 64 * 64; idx += 256) {    // W2 [n=64][k=64]
        int n = idx >> 6, k = idx & 63;
        float x = W2[idx];
        uint16_t hb = bf16_bits(x);
        uint16_t lb = bf16_bits(x - bf16_val(hb));
        g[(OFF_W2HI >> 1) + n * (S_W2 >> 1) + k] = hb;
        g[(OFF_W2LO >> 1) + n * (S_W2 >> 1) + k] = lb;
    }
}

// ---------------------------------------------------------------------------
// main: fused 2-layer MLP, 256 rows per CTA, tensor cores
// ---------------------------------------------------------------------------
__global__ void __launch_bounds__(THREADS, 1)
mlp_main(const float* __restrict__ audio, const float* __restrict__ video,
         const float* __restrict__ x1,    const float* __restrict__ x2,
         const float* __restrict__ b1,    const float* __restrict__ b2,
         float* __restrict__ out, long nrows) {
    extern __shared__ char smem[];
    const uint32_t sb = smem_u32(smem);

    // stage 0: copy pre-split weights (53 KB) into smem
    {
        uint4* dst = (uint4*)smem;
        for (int i = threadIdx.x; i < WBYTES / 16; i += THREADS)
            dst[i] = g_W[i];
    }
    __syncthreads();

    const int tid  = threadIdx.x;
    const int wid  = tid >> 5;
    const int lane = tid & 31;
    const int r = lane >> 2;      // fragment row 0..7
    const int q = lane & 3;       // fragment col quad

    const long row0   = (long)blockIdx.x * TM;
    const long orow   = row0 + wid * 16 + r;    // this thread's row (and +8)
    const bool full   = (row0 + TM) <= nrows;
    long lrow  = orow, lrow8 = orow + 8;        // clamped rows for loads
    if (!full) {
        long mx = nrows - 1;
        lrow  = lrow  < mx ? lrow  : mx;
        lrow8 = lrow8 < mx ? lrow8 : mx;
    }

    // per-lane ldmatrix base offsets (bytes)
    const int rowp = ((lane >> 4) & 1) * 8 + (lane & 7);  // row within 16-n strip
    const int kadd = ((lane >> 3) & 1) * 16;              // k half * 8 elems * 2B
    const uint32_t aW1hi = sb + OFF_W1HI + rowp * S_W1 + kadd;
    const uint32_t aW1lo = sb + OFF_W1LO + rowp * S_W1 + kadd;
    const uint32_t aW2hi = sb + OFF_W2HI + rowp * S_W2 + kadd;
    const uint32_t aW2lo = sb + OFF_W2LO + rowp * S_W2 + kadd;

    const float* mods[4] = {audio, video, x1, x2};

    // ---- GEMM1: acc[j] (j = ntile 0..7) = Xsplit @ W1split^T ----
    float acc[8][4];
#pragma unroll
    for (int j = 0; j < 8; j++)
#pragma unroll
        for (int i = 0; i < 4; i++) acc[j][i] = 0.f;

#pragma unroll
    for (int kt = 0; kt < 8; kt++) {
        const float* pm = mods[kt >> 1];
        const int    co = (kt & 1) * 16 + q * 2;
        float2 v00 = *(const float2*)(pm + lrow  * 32 + co);
        float2 v01 = *(const float2*)(pm + lrow  * 32 + co + 8);
        float2 v10 = *(const float2*)(pm + lrow8 * 32 + co);
        float2 v11 = *(const float2*)(pm + lrow8 * 32 + co + 8);

        uint32_t ah[4], al[4];
        split_pack(v00.x, v00.y, ah[0], al[0]);   // (r,   c)
        split_pack(v10.x, v10.y, ah[1], al[1]);   // (r+8, c)
        split_pack(v01.x, v01.y, ah[2], al[2]);   // (r,   c+8)
        split_pack(v11.x, v11.y, ah[3], al[3]);   // (r+8, c+8)

#pragma unroll
        for (int j = 0; j < 4; j++) {             // ntile pairs {2j, 2j+1}
            uint32_t bh[4], bl[4];
            ldsm4(bh, aW1hi + j * (16 * S_W1) + kt * 32);
            ldsm4(bl, aW1lo + j * (16 * S_W1) + kt * 32);
            mma_bf16(acc[2*j],   ah, bh[0], bh[1]);
            mma_bf16(acc[2*j],   ah, bl[0], bl[1]);
            mma_bf16(acc[2*j],   al, bh[0], bh[1]);
            mma_bf16(acc[2*j+1], ah, bh[2], bh[3]);
            mma_bf16(acc[2*j+1], ah, bl[2], bl[3]);
            mma_bf16(acc[2*j+1], al, bh[2], bh[3]);
        }
    }

    // ---- epilogue 1 (registers only): H = relu(acc + b1); split to bf16 ----
    uint32_t hhr[8], hhr8[8], hlr[8], hlr8[8];
#pragma unroll
    for (int j = 0; j < 8; j++) {
        float2 bv = *(const float2*)(b1 + j * 8 + q * 2);
        float h00 = fmaxf(acc[j][0] + bv.x, 0.f);
        float h01 = fmaxf(acc[j][1] + bv.y, 0.f);
        float h10 = fmaxf(acc[j][2] + bv.x, 0.f);
        float h11 = fmaxf(acc[j][3] + bv.y, 0.f);
        split_pack(h00, h01, hhr[j],  hlr[j]);    // row r
        split_pack(h10, h11, hhr8[j], hlr8[j]);   // row r+8
    }

    // ---- GEMM2: acc2 = Hsplit @ W2split^T ----
    float acc2[8][4];
#pragma unroll
    for (int j = 0; j < 8; j++)
#pragma unroll
        for (int i = 0; i < 4; i++) acc2[j][i] = 0.f;

#pragma unroll
    for (int t = 0; t < 4; t++) {                 // k-tiles of GEMM2
        uint32_t ah[4] = {hhr[2*t], hhr8[2*t], hhr[2*t+1], hhr8[2*t+1]};
        uint32_t al[4] = {hlr[2*t], hlr8[2*t], hlr[2*t+1], hlr8[2*t+1]};
#pragma unroll
        for (int j = 0; j < 4; j++) {
            uint32_t bh[4], bl[4];
            ldsm4(bh, aW2hi + j * (16 * S_W2) + t * 32);
            ldsm4(bl, aW2lo + j * (16 * S_W2) + t * 32);
            mma_bf16(acc2[2*j],   ah, bh[0], bh[1]);
            mma_bf16(acc2[2*j],   ah, bl[0], bl[1]);
            mma_bf16(acc2[2*j],   al, bh[0], bh[1]);
            mma_bf16(acc2[2*j+1], ah, bh[2], bh[3]);
            mma_bf16(acc2[2*j+1], ah, bl[2], bl[3]);
            mma_bf16(acc2[2*j+1], al, bh[2], bh[3]);
        }
    }

    // ---- epilogue 2: out = acc2 + b2 ----
    const bool st0 = full || (orow     < nrows);
    const bool st8 = full || (orow + 8 < nrows);
#pragma unroll
    for (int j = 0; j < 8; j++) {
        float2 bv = *(const float2*)(b2 + j * 8 + q * 2);
        if (st0) {
            float2 o = make_float2(acc2[j][0] + bv.x, acc2[j][1] + bv.y);
            *(float2*)(out + orow * 64 + j * 8 + q * 2) = o;
        }
        if (st8) {
            float2 o = make_float2(acc2[j][2] + bv.x, acc2[j][3] + bv.y);
            *(float2*)(out + (orow + 8) * 64 + j * 8 + q * 2) = o;
        }
    }
}

// ---------------------------------------------------------------------------
// rows 0..3 (graph nodes): exact fp32 fixup
// ---------------------------------------------------------------------------
__global__ void gcn_fixup_kernel(const float* __restrict__ audio,
                                 const float* __restrict__ video,
                                 const float* __restrict__ x1,
                                 const float* __restrict__ x2,
                                 const float* __restrict__ W1,
                                 const float* __restrict__ b1,
                                 const float* __restrict__ W2,
                                 const float* __restrict__ b2,
                                 float* __restrict__ out) {
    __shared__ float xbar[128];
    __shared__ float h[64];
    const int t = threadIdx.x;   // 128 threads
    {
        const float* mods[4] = {audio, video, x1, x2};
        const float* p = mods[t >> 5];
        int c = t & 31;
        xbar[t] = 0.25f * (p[c] + p[32 + c] + p[64 + c] + p[96 + c]);
    }
    __syncthreads();
    if (t < 64) {
        float s = 0.f;
        const float* wr = &W1[t * 128];
#pragma unroll 8
        for (int k = 0; k < 128; k++) s = fmaf(wr[k], xbar[k], s);
        h[t] = fmaxf(s + b1[t], 0.f);
    }
    __syncthreads();
    if (t < 64) {
        float s = 0.f;
        const float* wr = &W2[t * 64];
#pragma unroll 8
        for (int j = 0; j < 64; j++) s = fmaf(wr[j], h[j], s);
        float v = s + b2[t];
        out[0 * 64 + t] = v;
        out[1 * 64 + t] = v;
        out[2 * 64 + t] = v;
        out[3 * 64 + t] = v;
    }
}

extern "C" void kernel_launch(void* const* d_in, const int* in_sizes, int n_in,
                              void* d_out, int out_size) {
    const float* audio = (const float*)d_in[0];
    const float* video = (const float*)d_in[1];
    const float* x1    = (const float*)d_in[2];
    const float* x2    = (const float*)d_in[3];
    const float* W1    = (const float*)d_in[4];
    const float* b1    = (const float*)d_in[5];
    const float* W2    = (const float*)d_in[6];
    const float* b2    = (const float*)d_in[7];
    float* out = (float*)d_out;

    long nrows = (long)(in_sizes[0] / 32);
    int grid = (int)((nrows + TM - 1) / TM);

    cudaFuncSetAttribute(mlp_main, cudaFuncAttributeMaxDynamicSharedMemorySize,
                         WBYTES);

    prep_weights<<<1, 256>>>(W1, W2);
    mlp_main<<<grid, THREADS, WBYTES>>>(audio, video, x1, x2, b1, b2, out, nrows);
    gcn_fixup_kernel<<<1, 128>>>(audio, video, x1, x2, W1, b1, W2, b2, out);
}

// round 4
// speedup vs baseline: 2.9660x; 1.2597x over previous
#include <cuda_runtime.h>
#include <cuda_bf16.h>
#include <cstdint>

// ============================================================================
// out[i] = W2 @ relu(W1 @ x_i + b1) + b2  for i >= 4
// rows 0..3 all equal W2 @ relu(W1 @ mean(x_0..3) + b1) + b2
//
// Single fused kernel. Tensor cores via mma.sync m16n8k16 bf16.
// fp32 accuracy recovered with 2-way bf16 split, 3 accumulation passes.
// Per-CTA weight split (no prep kernel); block 0 does the 4-row graph fixup.
// ============================================================================

#define TM       128      // rows per CTA
#define THREADS  256      // 8 warps x 16 rows

// smem layout (bytes):
//   W1hi: [n=64][k=128] bf16, row stride 272  -> 17408
//   W1lo: +17408
//   W2hi: [n=64][k=64]  bf16, row stride 144  ->  9216
//   W2lo: +9216
#define S_W1     272
#define S_W2     144
#define OFF_W1HI 0
#define OFF_W1LO 17408
#define OFF_W2HI 34816
#define OFF_W2LO 44032
#define WBYTES   53248

__device__ __forceinline__ uint32_t smem_u32(const void* p) {
    uint32_t a;
    asm("{ .reg .u64 t; cvta.to.shared.u64 t, %1; cvt.u32.u64 %0, t; }"
        : "=r"(a) : "l"(p));
    return a;
}

// truncation split: hi = top 16 bits of each fp32 (1 PRMT for the pair),
// lo = rn(x - hi) packed via cvt.rn.bf16x2
__device__ __forceinline__ void split_pack(float x0, float x1,
                                           uint32_t& hi, uint32_t& lo) {
    uint32_t b0 = __float_as_uint(x0), b1 = __float_as_uint(x1);
    asm("prmt.b32 %0, %1, %2, 0x7632;" : "=r"(hi) : "r"(b0), "r"(b1));
    float r0 = x0 - __uint_as_float(b0 & 0xFFFF0000u);
    float r1 = x1 - __uint_as_float(b1 & 0xFFFF0000u);
    asm("cvt.rn.bf16x2.f32 %0, %1, %2;" : "=r"(lo) : "f"(r1), "f"(r0));
}

__device__ __forceinline__ void ldsm4(uint32_t* r, uint32_t addr) {
    asm volatile("ldmatrix.sync.aligned.m8n8.x4.shared.b16 {%0,%1,%2,%3}, [%4];"
                 : "=r"(r[0]), "=r"(r[1]), "=r"(r[2]), "=r"(r[3])
                 : "r"(addr));
}

__device__ __forceinline__ void mma_bf16(float* d, const uint32_t* a,
                                         uint32_t b0, uint32_t b1) {
    asm volatile(
        "mma.sync.aligned.m16n8k16.row.col.f32.bf16.bf16.f32 "
        "{%0,%1,%2,%3}, {%4,%5,%6,%7}, {%8,%9}, {%0,%1,%2,%3};"
        : "+f"(d[0]), "+f"(d[1]), "+f"(d[2]), "+f"(d[3])
        : "r"(a[0]), "r"(a[1]), "r"(a[2]), "r"(a[3]), "r"(b0), "r"(b1));
}

__global__ void __launch_bounds__(THREADS, 2)
mlp_main(const float* __restrict__ audio, const float* __restrict__ video,
         const float* __restrict__ x1,    const float* __restrict__ x2,
         const float* __restrict__ W1,    const float* __restrict__ b1,
         const float* __restrict__ W2,    const float* __restrict__ b2,
         float* __restrict__ out, long nrows) {
    extern __shared__ char smem[];
    const uint32_t sb = smem_u32(smem);
    const int tid = threadIdx.x;

    // ---- stage 0: load fp32 weights, split to bf16 hi/lo in smem ----
    {
        const float4* W1f4 = (const float4*)W1;   // 2048 float4
        const float4* W2f4 = (const float4*)W2;   // 1024 float4
#pragma unroll
        for (int it = 0; it < 12; it++) {         // 3072 float4 total
            int i = tid + it * THREADS;
            float4 v;
            uint32_t off_hi, off_lo;
            if (i < 2048) {
                v = W1f4[i];
                int n = i >> 5, k4 = i & 31;
                off_hi = OFF_W1HI + n * S_W1 + k4 * 8;
                off_lo = OFF_W1LO + n * S_W1 + k4 * 8;
            } else {
                int j = i - 2048;
                v = W2f4[j];
                int n = j >> 4, k4 = j & 15;
                off_hi = OFF_W2HI + n * S_W2 + k4 * 8;
                off_lo = OFF_W2LO + n * S_W2 + k4 * 8;
            }
            uint2 hp, lp;
            split_pack(v.x, v.y, hp.x, lp.x);
            split_pack(v.z, v.w, hp.y, lp.y);
            *(uint2*)(smem + off_hi) = hp;
            *(uint2*)(smem + off_lo) = lp;
        }
    }
    __syncthreads();

    const int wid  = tid >> 5;
    const int lane = tid & 31;
    const int r = lane >> 2;      // fragment row 0..7
    const int q = lane & 3;       // fragment col quad

    const long row0 = (long)blockIdx.x * TM;
    const long orow = row0 + wid * 16 + r;     // this thread's row (and +8)
    const bool full = (row0 + TM) <= nrows;
    long lrow = orow, lrow8 = orow + 8;
    if (!full) {
        long mx = nrows - 1;
        lrow  = lrow  < mx ? lrow  : mx;
        lrow8 = lrow8 < mx ? lrow8 : mx;
    }

    // per-lane ldmatrix base offsets
    const int rowp = ((lane >> 4) & 1) * 8 + (lane & 7);
    const int kadd = ((lane >> 3) & 1) * 16;
    const uint32_t aW1hi = sb + OFF_W1HI + rowp * S_W1 + kadd;
    const uint32_t aW1lo = sb + OFF_W1LO + rowp * S_W1 + kadd;
    const uint32_t aW2hi = sb + OFF_W2HI + rowp * S_W2 + kadd;
    const uint32_t aW2lo = sb + OFF_W2LO + rowp * S_W2 + kadd;

    const float* mods[4] = {audio, video, x1, x2};

    // ---- GEMM1: acc[j] = Xsplit @ W1split^T  (8 k-tiles of 16) ----
    float acc[8][4];
#pragma unroll
    for (int j = 0; j < 8; j++)
#pragma unroll
        for (int i = 0; i < 4; i++) acc[j][i] = 0.f;

    // prefetch kt=0
    float2 p00, p01, p10, p11;
    {
        const float* pm = mods[0];
        const int co = q * 2;
        p00 = *(const float2*)(pm + lrow  * 32 + co);
        p01 = *(const float2*)(pm + lrow  * 32 + co + 8);
        p10 = *(const float2*)(pm + lrow8 * 32 + co);
        p11 = *(const float2*)(pm + lrow8 * 32 + co + 8);
    }

#pragma unroll
    for (int kt = 0; kt < 8; kt++) {
        float2 n00, n01, n10, n11;
        if (kt < 7) {                              // prefetch kt+1
            const float* pm = mods[(kt + 1) >> 1];
            const int co = ((kt + 1) & 1) * 16 + q * 2;
            n00 = *(const float2*)(pm + lrow  * 32 + co);
            n01 = *(const float2*)(pm + lrow  * 32 + co + 8);
            n10 = *(const float2*)(pm + lrow8 * 32 + co);
            n11 = *(const float2*)(pm + lrow8 * 32 + co + 8);
        }

        uint32_t ah[4], al[4];
        split_pack(p00.x, p00.y, ah[0], al[0]);    // (r,   c)
        split_pack(p10.x, p10.y, ah[1], al[1]);    // (r+8, c)
        split_pack(p01.x, p01.y, ah[2], al[2]);    // (r,   c+8)
        split_pack(p11.x, p11.y, ah[3], al[3]);    // (r+8, c+8)

#pragma unroll
        for (int j = 0; j < 4; j++) {              // n-tile pairs {2j, 2j+1}
            uint32_t bh[4], bl[4];
            ldsm4(bh, aW1hi + j * (16 * S_W1) + kt * 32);
            ldsm4(bl, aW1lo + j * (16 * S_W1) + kt * 32);
            mma_bf16(acc[2*j],   ah, bh[0], bh[1]);
            mma_bf16(acc[2*j],   ah, bl[0], bl[1]);
            mma_bf16(acc[2*j],   al, bh[0], bh[1]);
            mma_bf16(acc[2*j+1], ah, bh[2], bh[3]);
            mma_bf16(acc[2*j+1], ah, bl[2], bl[3]);
            mma_bf16(acc[2*j+1], al, bh[2], bh[3]);
        }
        p00 = n00; p01 = n01; p10 = n10; p11 = n11;
    }

    // ---- epilogue 1 (registers only): H = relu(acc + b1); split ----
    uint32_t hhr[8], hhr8[8], hlr[8], hlr8[8];
#pragma unroll
    for (int j = 0; j < 8; j++) {
        float2 bv = *(const float2*)(b1 + j * 8 + q * 2);
        float h00 = fmaxf(acc[j][0] + bv.x, 0.f);
        float h01 = fmaxf(acc[j][1] + bv.y, 0.f);
        float h10 = fmaxf(acc[j][2] + bv.x, 0.f);
        float h11 = fmaxf(acc[j][3] + bv.y, 0.f);
        split_pack(h00, h01, hhr[j],  hlr[j]);
        split_pack(h10, h11, hhr8[j], hlr8[j]);
    }

    // ---- GEMM2: acc2 = Hsplit @ W2split^T ----
    float acc2[8][4];
#pragma unroll
    for (int j = 0; j < 8; j++)
#pragma unroll
        for (int i = 0; i < 4; i++) acc2[j][i] = 0.f;

#pragma unroll
    for (int t = 0; t < 4; t++) {
        uint32_t ah[4] = {hhr[2*t], hhr8[2*t], hhr[2*t+1], hhr8[2*t+1]};
        uint32_t al[4] = {hlr[2*t], hlr8[2*t], hlr[2*t+1], hlr8[2*t+1]};
#pragma unroll
        for (int j = 0; j < 4; j++) {
            uint32_t bh[4], bl[4];
            ldsm4(bh, aW2hi + j * (16 * S_W2) + t * 32);
            ldsm4(bl, aW2lo + j * (16 * S_W2) + t * 32);
            mma_bf16(acc2[2*j],   ah, bh[0], bh[1]);
            mma_bf16(acc2[2*j],   ah, bl[0], bl[1]);
            mma_bf16(acc2[2*j],   al, bh[0], bh[1]);
            mma_bf16(acc2[2*j+1], ah, bh[2], bh[3]);
            mma_bf16(acc2[2*j+1], ah, bl[2], bl[3]);
            mma_bf16(acc2[2*j+1], al, bh[2], bh[3]);
        }
    }

    // ---- epilogue 2: out = acc2 + b2 ----
    const bool st0 = full || (orow     < nrows);
    const bool st8 = full || (orow + 8 < nrows);
#pragma unroll
    for (int j = 0; j < 8; j++) {
        float2 bv = *(const float2*)(b2 + j * 8 + q * 2);
        if (st0) {
            float2 o = make_float2(acc2[j][0] + bv.x, acc2[j][1] + bv.y);
            *(float2*)(out + orow * 64 + j * 8 + q * 2) = o;
        }
        if (st8) {
            float2 o = make_float2(acc2[j][2] + bv.x, acc2[j][3] + bv.y);
            *(float2*)(out + (orow + 8) * 64 + j * 8 + q * 2) = o;
        }
    }

    // ---- block 0: exact fp32 fixup for graph rows 0..3 ----
    if (blockIdx.x == 0) {
        __syncthreads();                 // rows 0..3 stored above by this block
        float* xbar = (float*)smem;      // weights in smem are dead now
        float* h    = xbar + 128;
        const int t = tid;
        if (t < 128) {
            const float* p = mods[t >> 5];
            int c = t & 31;
            xbar[t] = 0.25f * (p[c] + p[32 + c] + p[64 + c] + p[96 + c]);
        }
        __syncthreads();
        if (t < 64) {
            float s = 0.f;
            const float* wr = &W1[t * 128];
#pragma unroll 8
            for (int k = 0; k < 128; k++) s = fmaf(wr[k], xbar[k], s);
            h[t] = fmaxf(s + b1[t], 0.f);
        }
        __syncthreads();
        if (t < 64) {
            float s = 0.f;
            const float* wr = &W2[t * 64];
#pragma unroll 8
            for (int j = 0; j < 64; j++) s = fmaf(wr[j], h[j], s);
            float v = s + b2[t];
            out[0 * 64 + t] = v;
            out[1 * 64 + t] = v;
            out[2 * 64 + t] = v;
            out[3 * 64 + t] = v;
        }
    }
}

extern "C" void kernel_launch(void* const* d_in, const int* in_sizes, int n_in,
                              void* d_out, int out_size) {
    const float* audio = (const float*)d_in[0];
    const float* video = (const float*)d_in[1];
    const float* x1    = (const float*)d_in[2];
    const float* x2    = (const float*)d_in[3];
    const float* W1    = (const float*)d_in[4];
    const float* b1    = (const float*)d_in[5];
    const float* W2    = (const float*)d_in[6];
    const float* b2    = (const float*)d_in[7];
    float* out = (float*)d_out;

    long nrows = (long)(in_sizes[0] / 32);
    int grid = (int)((nrows + TM - 1) / TM);

    cudaFuncSetAttribute(mlp_main, cudaFuncAttributeMaxDynamicSharedMemorySize,
                         WBYTES);

    mlp_main<<<grid, THREADS, WBYTES>>>(audio, video, x1, x2, W1, b1, W2, b2,
                                        out, nrows);
}